// round 12
// baseline (speedup 1.0000x reference)
#include <cuda_runtime.h>
#include <math_constants.h>

typedef unsigned int u32;

// img (1,200,200,512) f32 NHWC, rois (1,128,4) f32 (x,y,w,h), pool 7x7
// out (1,128,7,7,512) f32.
#define IMG_H 200
#define IMG_W 200
#define IMG_C 512
#define C4    128               // float4 per pixel record
#define POOLP 7
#define NROIS 128
#define NBINS 49
#define NBIN_TOT (NROIS * NBINS)   // 6272

#define TW 20
#define TH 20
#define NTX 10
#define NTY 10
#define NTILES (NTX * NTY)      // 100

#define NCHUNK 16               // channel chunks per tile
#define CH4    8                // float4 per chunk (32 channels)

#define TLIST_CAP NBIN_TOT      // provable worst case: 1 entry per bin per tile

// ---- device scratch (static: allocation-free) ----------------------------
__device__ u32    g_rect[NBIN_TOT];          // per-bin (bx0,bx1,by0,by1) packed
__device__ int    g_listcnt[NTILES];
__device__ uint2  g_list[NTILES][TLIST_CAP]; // 5.0 MB
// Partial maxima for bins spanning >1 tile: [bin][sy*2+sx][128 float4].
// Only written subslots are ever read -> no init needed.
__device__ float4 g_partial[(size_t)NBIN_TOT * 4 * C4];   // 51.4 MB

// ---- kernel 1: bounds + per-tile worklists (one CTA per tile) ------------
// Boundary math must match JAX f32 op order exactly: step = w/7;
// b[k] = int(x + k*step), mul then add, NO fma contraction.
__global__ __launch_bounds__(256) void list_kernel(const float* __restrict__ rois)
{
    __shared__ short s_bx[NROIS][8];
    __shared__ short s_by[NROIS][8];
    __shared__ int   s_cnt;

    const int tid  = threadIdx.x;
    const int tile = blockIdx.x;
    const int tx = tile % NTX, ty = tile / NTX;
    const int x0 = tx * TW,    y0 = ty * TH;

    if (tid == 0) s_cnt = 0;
    if (tid < NROIS) {
        float rx = rois[tid * 4 + 0], ry = rois[tid * 4 + 1];
        float rw = rois[tid * 4 + 2], rh = rois[tid * 4 + 3];
        float sx = __fdiv_rn(rw, 7.0f);
        float sy = __fdiv_rn(rh, 7.0f);
        #pragma unroll
        for (int k = 0; k < 8; k++) {
            s_bx[tid][k] = (short)(int)__fadd_rn(rx, __fmul_rn((float)k, sx));
            s_by[tid][k] = (short)(int)__fadd_rn(ry, __fmul_rn((float)k, sy));
        }
    }
    __syncthreads();

    // every thread: test 6272/256 = 24.5 bins against this tile
    for (int b = tid; b < NBIN_TOT; b += 256) {
        int r   = b / NBINS;
        int bin = b - r * NBINS;
        int jy  = bin / POOLP;
        int ix  = bin - jy * POOLP;
        int rx0 = s_bx[r][ix], rx1 = s_bx[r][ix + 1];
        int ry0 = s_by[r][jy], ry1 = s_by[r][jy + 1];

        if (tile == 0)   // one CTA publishes rects for the reduce kernel
            g_rect[b] = (u32)rx0 | ((u32)rx1 << 8) |
                        ((u32)ry0 << 16) | ((u32)ry1 << 24);

        int cl = max(rx0 - x0, 0), ch = min(rx1 - x0, TW);
        int rl = max(ry0 - y0, 0), rh = min(ry1 - y0, TH);
        if (cl < ch && rl < rh) {
            int tx0 = rx0 / TW, ty0 = ry0 / TH;
            bool single = (tx0 == (rx1 - 1) / TW) && (ty0 == (ry1 - 1) / TH);
            u32 dst = single ? ((u32)b | 0x80000000u)
                             : (u32)(b * 4 + (ty - ty0) * 2 + (tx - tx0));
            int idx = atomicAdd(&s_cnt, 1);
            g_list[tile][idx] = make_uint2(
                (u32)rl | ((u32)rh << 5) | ((u32)cl << 10) | ((u32)ch << 15),
                dst);
        }
    }
    __syncthreads();
    if (tid == 0) g_listcnt[tile] = s_cnt;
}

// ---- kernel 2: tile sweep ------------------------------------------------
// CTA = (20x20 px tile, 32-channel chunk). Stage 51.2 KB slab into SMEM,
// then ONE ENTRY PER WARP (uniform control flow): lane = px(4) x c4(8).
// Each LDS.128 covers 4 consecutive pixels x 32 ch = 512 B, conflict-free;
// predicated-off lanes emit no crossbar traffic. 8 shuffles fold px.
__global__ __launch_bounds__(256, 4) void tile_kernel(const float4* __restrict__ img4,
                                                      float4* __restrict__ out4)
{
    extern __shared__ float4 tilebuf[];          // 3200 float4

    const int tid   = threadIdx.x;
    const int chunk = blockIdx.x & (NCHUNK - 1);
    const int tile  = blockIdx.x >> 4;
    const int tx = tile % NTX, ty = tile / NTX;
    const int x0 = tx * TW,    y0 = ty * TH;

    // -- stage slab: 3200 float4, coalesced --------------------------------
    {
        const float4* __restrict__ src = img4 + chunk * CH4;
        for (int i = tid; i < TH * TW * CH4; i += 256) {
            int p = i >> 3;                      // pixel 0..399
            int c = i & 7;
            int py = p / TW;
            int px = p - py * TW;
            tilebuf[i] = src[((y0 + py) * IMG_W + (x0 + px)) * C4 + c];
        }
    }
    const int n = g_listcnt[tile];
    const uint2* __restrict__ lst = g_list[tile];
    __syncthreads();

    const int warp = tid >> 5;
    const int lane = tid & 31;
    const int c    = lane & 7;                   // float4 channel slot
    const int px   = lane >> 3;                  // pixel offset 0..3

    for (int e = warp; e < n; e += 8) {
        uint2 en = __ldg(&lst[e]);               // broadcast load
        int rl = en.x & 31, rh = (en.x >> 5) & 31;
        int cl = (en.x >> 10) & 31, ch = (en.x >> 15) & 31;
        int nx = ch - cl;

        float4 m = make_float4(-CUDART_INF_F, -CUDART_INF_F,
                               -CUDART_INF_F, -CUDART_INF_F);
        for (int y = rl; y < rh; y++) {
            int base = (y * TW + cl) * CH4 + c;
            for (int xb = 0; xb < nx; xb += 4) {
                int xx = xb + px;
                if (xx < nx) {
                    float4 v = tilebuf[base + xx * CH4];
                    m.x = fmaxf(m.x, v.x); m.y = fmaxf(m.y, v.y);
                    m.z = fmaxf(m.z, v.z); m.w = fmaxf(m.w, v.w);
                }
            }
        }
        // fold the 4 pixel lanes (xor 8, 16)
        #pragma unroll
        for (int o = 8; o < 32; o <<= 1) {
            m.x = fmaxf(m.x, __shfl_xor_sync(0xffffffffu, m.x, o));
            m.y = fmaxf(m.y, __shfl_xor_sync(0xffffffffu, m.y, o));
            m.z = fmaxf(m.z, __shfl_xor_sync(0xffffffffu, m.z, o));
            m.w = fmaxf(m.w, __shfl_xor_sync(0xffffffffu, m.w, o));
        }
        if (px == 0) {
            float4* dst = (en.y & 0x80000000u)
                        ? out4 + (size_t)(en.y & 0x7fffffffu) * C4
                        : g_partial + (size_t)en.y * C4;
            dst[chunk * CH4 + c] = m;
        }
    }
}

// ---- kernel 3: combine split-bin partials --------------------------------
__global__ __launch_bounds__(128) void reduce_kernel(float4* __restrict__ out4)
{
    const int bid = blockIdx.x;
    u32 rc = g_rect[bid];
    int bx0 = rc & 255, bx1 = (rc >> 8) & 255;
    int by0 = (rc >> 16) & 255, by1 = rc >> 24;
    int ntx = (bx1 - 1) / TW - bx0 / TW + 1;   // 1 or 2
    int nty = (by1 - 1) / TH - by0 / TH + 1;   // 1 or 2
    if (ntx == 1 && nty == 1) return;          // tile kernel wrote out directly

    const int tid = threadIdx.x;
    float4 m = make_float4(-CUDART_INF_F, -CUDART_INF_F,
                           -CUDART_INF_F, -CUDART_INF_F);
    #pragma unroll 1
    for (int sy = 0; sy < nty; sy++)
        #pragma unroll 1
        for (int sx = 0; sx < ntx; sx++) {
            float4 v = g_partial[(size_t)(bid * 4 + sy * 2 + sx) * C4 + tid];
            m.x = fmaxf(m.x, v.x); m.y = fmaxf(m.y, v.y);
            m.z = fmaxf(m.z, v.z); m.w = fmaxf(m.w, v.w);
        }
    out4[(size_t)bid * C4 + tid] = m;
}

// ---- launch --------------------------------------------------------------
extern "C" void kernel_launch(void* const* d_in, const int* in_sizes, int n_in,
                              void* d_out, int out_size)
{
    const float* img  = (const float*)d_in[0];
    const float* rois = (const float*)d_in[1];
    float4* out = (float4*)d_out;

    const int smem_bytes = TH * TW * CH4 * (int)sizeof(float4);  // 51200
    cudaFuncSetAttribute(tile_kernel,
                         cudaFuncAttributeMaxDynamicSharedMemorySize, smem_bytes);

    list_kernel<<<NTILES, 256>>>(rois);
    tile_kernel<<<NTILES * NCHUNK, 256, smem_bytes>>>((const float4*)img, out);
    reduce_kernel<<<NBIN_TOT, 128>>>(out);
}

// round 13
// speedup vs baseline: 1.3991x; 1.3991x over previous
#include <cuda_runtime.h>
#include <math_constants.h>

typedef unsigned int u32;

// img (1,200,200,512) f32 NHWC, rois (1,128,4) f32 (x,y,w,h), pool 7x7
// out (1,128,7,7,512) f32.
#define IMG_H 200
#define IMG_W 200
#define IMG_C 512
#define C4    128               // float4 per full pixel record
#define POOLP 7
#define NROIS 128
#define NBINS 49
#define NBIN_TOT (NROIS * NBINS)   // 6272

#define TW 20
#define TH 20
#define NTX 10
#define NTY 10
#define NTILES (NTX * NTY)      // 100

#define NCHUNK 4                // channel chunks per tile (128 ch each)
#define CH4    32               // float4 per chunk per pixel
#define SLAB   (TH * TW * CH4)  // 12800 float4 = 204800 B

#define LCAP   256              // SMEM worklist entries (avg ~97/tile); overflow -> global

// ---- device scratch (static: allocation-free) ----------------------------
__device__ int    g_listcnt[NTILES];
__device__ uint2  g_list[NTILES][NBIN_TOT];  // provable cap: 1 entry/bin/tile
// Partial maxima for bins spanning >1 tile: [bin][sy*2+sx][128 float4].
// Only written subslots are ever read -> no init needed.
__device__ float4 g_partial[(size_t)NBIN_TOT * 4 * C4];   // 51.4 MB

// Exact JAX f32 boundary: step = w/7; b[k] = int(x + k*step); mul->add, no fma.
__device__ __forceinline__ int bin_edge(float base, float step, int k) {
    return (int)__fadd_rn(base, __fmul_rn((float)k, step));
}

// ---- kernel 1: per-tile worklists (CTA per tile, bbox-pruned) ------------
__global__ __launch_bounds__(128) void list_kernel(const float* __restrict__ rois)
{
    __shared__ short s_bx[NROIS][8];
    __shared__ short s_by[NROIS][8];
    __shared__ unsigned char s_hit[NROIS];
    __shared__ int s_nhit, s_cnt;

    const int tid  = threadIdx.x;
    const int tile = blockIdx.x;
    const int tx = tile % NTX, ty = tile / NTX;
    const int x0 = tx * TW,    y0 = ty * TH;

    if (tid == 0) { s_nhit = 0; s_cnt = 0; }
    __syncthreads();

    // phase A: bounds for all ROIs + bbox test vs this tile
    {
        const int r = tid;
        float rx = rois[r * 4 + 0], ry = rois[r * 4 + 1];
        float rw = rois[r * 4 + 2], rh = rois[r * 4 + 3];
        float sx = __fdiv_rn(rw, 7.0f);
        float sy = __fdiv_rn(rh, 7.0f);
        int b0x = 0, b7x = 0, b0y = 0, b7y = 0;
        #pragma unroll
        for (int k = 0; k < 8; k++) {
            int vx = bin_edge(rx, sx, k);
            int vy = bin_edge(ry, sy, k);
            s_bx[r][k] = (short)vx;
            s_by[r][k] = (short)vy;
            if (k == 0) { b0x = vx; b0y = vy; }
            if (k == 7) { b7x = vx; b7y = vy; }
        }
        if (b0x < x0 + TW && b7x > x0 && b0y < y0 + TH && b7y > y0) {
            int idx = atomicAdd(&s_nhit, 1);
            s_hit[idx] = (unsigned char)r;
        }
    }
    __syncthreads();

    // phase B: expand hit ROIs' bins (~10 ROIs * 49 bins)
    const int units = s_nhit * NBINS;
    for (int u = tid; u < units; u += 128) {
        int r   = s_hit[u / NBINS];
        int bin = u % NBINS;
        int jy  = bin / POOLP;
        int ix  = bin - jy * POOLP;
        int rx0 = s_bx[r][ix], rx1 = s_bx[r][ix + 1];
        int ry0 = s_by[r][jy], ry1 = s_by[r][jy + 1];

        int cl = max(rx0 - x0, 0), ch = min(rx1 - x0, TW);
        int rl = max(ry0 - y0, 0), rh = min(ry1 - y0, TH);
        if (cl < ch && rl < rh) {
            int tx0 = rx0 / TW, ty0 = ry0 / TH;
            bool single = (tx0 == (rx1 - 1) / TW) && (ty0 == (ry1 - 1) / TH);
            int bid = r * NBINS + bin;
            u32 dst = single ? ((u32)bid | 0x80000000u)
                             : (u32)(bid * 4 + (ty - ty0) * 2 + (tx - tx0));
            int idx = atomicAdd(&s_cnt, 1);
            g_list[tile][idx] = make_uint2(
                (u32)rl | ((u32)rh << 5) | ((u32)cl << 10) | ((u32)ch << 15),
                dst);
        }
    }
    __syncthreads();
    if (tid == 0) g_listcnt[tile] = s_cnt;
}

// ---- kernel 2: tile sweep ------------------------------------------------
// CTA = (20x20 tile, 128-channel chunk), 512 threads, 204.8 KB slab,
// 1 CTA/SM. Warp per entry, lane = channel: every LDS.128 is a full
// 512 B conflict-free wavefront set. No predication, no shuffles.
__global__ __launch_bounds__(512, 1) void tile_kernel(const float4* __restrict__ img4,
                                                      float4* __restrict__ out4)
{
    extern __shared__ float4 smem[];
    float4* tilebuf = smem;                       // SLAB float4
    uint2*  s_list  = (uint2*)(smem + SLAB);      // LCAP entries

    const int tid   = threadIdx.x;
    const int chunk = blockIdx.x & (NCHUNK - 1);
    const int tile  = blockIdx.x >> 2;
    const int tx = tile % NTX, ty = tile / NTX;
    const int x0 = tx * TW,    y0 = ty * TH;

    // -- stage slab: 12800 float4, 25 per thread, coalesced 512B/warp ------
    {
        const float4* __restrict__ src = img4 + chunk * CH4;
        #pragma unroll 5
        for (int i = tid; i < SLAB; i += 512) {
            int p = i >> 5;                       // pixel 0..399
            int c = i & 31;
            int py = p / TW;
            int px = p - py * TW;
            tilebuf[i] = src[((y0 + py) * IMG_W + (x0 + px)) * C4 + c];
        }
    }
    const int n = g_listcnt[tile];
    const uint2* __restrict__ glst = g_list[tile];
    for (int e = tid; e < n && e < LCAP; e += 512)
        s_list[e] = glst[e];
    __syncthreads();

    const int warp = tid >> 5;                    // 16 warps
    const int c    = tid & 31;                    // channel float4 slot

    for (int e = warp; e < n; e += 16) {
        uint2 en = (e < LCAP) ? s_list[e] : __ldg(&glst[e]);
        int rl = en.x & 31, rh = (en.x >> 5) & 31;
        int cl = (en.x >> 10) & 31, ch = (en.x >> 15) & 31;
        int nx = ch - cl;

        float4 m0 = make_float4(-CUDART_INF_F, -CUDART_INF_F,
                                -CUDART_INF_F, -CUDART_INF_F);
        float4 m1 = m0;
        for (int y = rl; y < rh; y++) {
            const float4* rp = tilebuf + (y * TW + cl) * CH4 + c;
            int x = 0;
            for (; x + 1 < nx; x += 2) {          // 2 accumulators (ILP)
                float4 v0 = rp[x * CH4];
                float4 v1 = rp[(x + 1) * CH4];
                m0.x = fmaxf(m0.x, v0.x); m0.y = fmaxf(m0.y, v0.y);
                m0.z = fmaxf(m0.z, v0.z); m0.w = fmaxf(m0.w, v0.w);
                m1.x = fmaxf(m1.x, v1.x); m1.y = fmaxf(m1.y, v1.y);
                m1.z = fmaxf(m1.z, v1.z); m1.w = fmaxf(m1.w, v1.w);
            }
            if (x < nx) {
                float4 v0 = rp[x * CH4];
                m0.x = fmaxf(m0.x, v0.x); m0.y = fmaxf(m0.y, v0.y);
                m0.z = fmaxf(m0.z, v0.z); m0.w = fmaxf(m0.w, v0.w);
            }
        }
        m0.x = fmaxf(m0.x, m1.x); m0.y = fmaxf(m0.y, m1.y);
        m0.z = fmaxf(m0.z, m1.z); m0.w = fmaxf(m0.w, m1.w);

        float4* dst = (en.y & 0x80000000u)
                    ? out4 + (size_t)(en.y & 0x7fffffffu) * C4
                    : g_partial + (size_t)en.y * C4;
        dst[chunk * CH4 + c] = m0;                // 512B coalesced store
    }
}

// ---- kernel 3: combine split-bin partials (recomputes bounds) ------------
__global__ __launch_bounds__(128) void reduce_kernel(const float* __restrict__ rois,
                                                     float4* __restrict__ out4)
{
    const int bid = blockIdx.x;                   // r*49 + jy*7 + ix
    int r   = bid / NBINS;
    int bin = bid - r * NBINS;
    int jy  = bin / POOLP;
    int ix  = bin - jy * POOLP;

    float rx = rois[r * 4 + 0], ry = rois[r * 4 + 1];
    float rw = rois[r * 4 + 2], rh = rois[r * 4 + 3];
    float sx = __fdiv_rn(rw, 7.0f);
    float sy = __fdiv_rn(rh, 7.0f);
    int bx0 = bin_edge(rx, sx, ix), bx1 = bin_edge(rx, sx, ix + 1);
    int by0 = bin_edge(ry, sy, jy), by1 = bin_edge(ry, sy, jy + 1);

    int ntx = (bx1 - 1) / TW - bx0 / TW + 1;      // 1 or 2
    int nty = (by1 - 1) / TH - by0 / TH + 1;      // 1 or 2
    if (ntx == 1 && nty == 1) return;             // tile kernel wrote directly

    const int tid = threadIdx.x;
    float4 m = make_float4(-CUDART_INF_F, -CUDART_INF_F,
                           -CUDART_INF_F, -CUDART_INF_F);
    #pragma unroll 1
    for (int sy2 = 0; sy2 < nty; sy2++)
        #pragma unroll 1
        for (int sx2 = 0; sx2 < ntx; sx2++) {
            float4 v = g_partial[(size_t)(bid * 4 + sy2 * 2 + sx2) * C4 + tid];
            m.x = fmaxf(m.x, v.x); m.y = fmaxf(m.y, v.y);
            m.z = fmaxf(m.z, v.z); m.w = fmaxf(m.w, v.w);
        }
    out4[(size_t)bid * C4 + tid] = m;
}

// ---- launch --------------------------------------------------------------
extern "C" void kernel_launch(void* const* d_in, const int* in_sizes, int n_in,
                              void* d_out, int out_size)
{
    const float* img  = (const float*)d_in[0];
    const float* rois = (const float*)d_in[1];
    float4* out = (float4*)d_out;

    const int smem_bytes = SLAB * (int)sizeof(float4)        // 204800
                         + LCAP * (int)sizeof(uint2);        // 2048
    cudaFuncSetAttribute(tile_kernel,
                         cudaFuncAttributeMaxDynamicSharedMemorySize, smem_bytes);

    list_kernel<<<NTILES, 128>>>(rois);
    tile_kernel<<<NTILES * NCHUNK, 512, smem_bytes>>>((const float4*)img, out);
    reduce_kernel<<<NBIN_TOT, 128>>>(rois, out);
}